// round 9
// baseline (speedup 1.0000x reference)
#include <cuda_runtime.h>
#include <cstdint>

// CenterLoss: mean_i ||x_i - centers[labels_i]||^2
//   = mean( ||x||^2 + ||c||^2 - 2 x.c )
// x: [4096, 512] f32, centers: [7001, 512] f32, labels: [4096] i32 -> out: [1] f32

#define BATCH 4096
#define DIM 512
#define VEC (DIM / 4)     // 128 float4 per row
#define NBLK 512
#define BLOCK 256
#define SPB 8             // samples per block (4 per 128-thread half) -> exact balance

__device__ float g_accum = 0.0f;       // single pre-scaled accumulator
__device__ unsigned int g_count = 0;

// Packed fp32x2 helpers (Blackwell): one instruction = two independent fp32 FMAs.
#define PACK2(dst, lo, hi) \
    asm("mov.b64 %0, {%1, %2};" : "=l"(dst) : "f"(lo), "f"(hi))
#define FMA2(acc, a, b) \
    asm("fma.rn.f32x2 %0, %1, %2, %0;" : "+l"(acc) : "l"(a), "l"(b))
#define UNPACK2(lo, hi, src) \
    asm("mov.b64 {%0, %1}, %2;" : "=f"(lo), "=f"(hi) : "l"(src))

__global__ __launch_bounds__(BLOCK, 4)
void center_loss_kernel(const float4* __restrict__ x,
                        const float4* __restrict__ c,
                        const int4* __restrict__ labels4,
                        float* __restrict__ out)
{
    const int t = threadIdx.x;        // 0..255
    const int b = blockIdx.x;
    const int h = t >> 7;             // half 0/1 -> samples [4h, 4h+4)
    const int lane128 = t & 127;      // float4 lane within a row
    const int base = b * SPB + h * 4;

    // One int4 per half: the dependent center gather issues ASAP after this.
    const int4 lv = __ldg(&labels4[b * 2 + h]);
    const int labs[4] = { lv.x, lv.y, lv.z, lv.w };

    // Decomposed accumulation with packed f32x2 FMAs: 6 FFMA2 per sample
    // instead of 12 FFMA; every loaded float4 still consumed independently.
    uint64_t axx2 = 0ull, acc2 = 0ull, axc2 = 0ull;
#pragma unroll
    for (int s = 0; s < 4; s++) {
        float4 xv = x[(base + s) * VEC + lane128];
        uint64_t x01, x23;
        PACK2(x01, xv.x, xv.y);
        PACK2(x23, xv.z, xv.w);
        FMA2(axx2, x01, x01);
        FMA2(axx2, x23, x23);
        float4 cv = c[labs[s] * VEC + lane128];
        uint64_t c01, c23;
        PACK2(c01, cv.x, cv.y);
        PACK2(c23, cv.z, cv.w);
        FMA2(acc2, c01, c01);
        FMA2(acc2, c23, c23);
        FMA2(axc2, x01, c01);
        FMA2(axc2, x23, c23);
    }
    float a0, a1, b0, b1, d0, d1;
    UNPACK2(a0, a1, axx2);
    UNPACK2(b0, b1, acc2);
    UNPACK2(d0, d1, axc2);
    float acc = (a0 + a1) + (b0 + b1) - 2.0f * (d0 + d1);

    // Warp reduce
#pragma unroll
    for (int o = 16; o; o >>= 1) acc += __shfl_xor_sync(0xffffffffu, acc, o);

    __shared__ float ws[BLOCK / 32];
    if ((t & 31) == 0) ws[t >> 5] = acc;
    __syncthreads();

    // Thread 0: one pre-scaled RED + acq_rel ticket; last CTA reads 1 float.
    if (t == 0) {
        float p = 0.0f;
#pragma unroll
        for (int w = 0; w < BLOCK / 32; w++) p += ws[w];
        // Posted reduction (no return), pre-scaled so accumulator == mean.
        asm volatile("red.add.relaxed.gpu.global.f32 [%0], %1;"
                     :: "l"(&g_accum), "f"(p * (1.0f / (float)BATCH))
                     : "memory");
        // Release orders the RED above; acquire covers the read below.
        unsigned int v;
        asm volatile("atom.add.acq_rel.gpu.global.u32 %0, [%1], 1;"
                     : "=r"(v) : "l"(&g_count) : "memory");
        if (v == NBLK - 1) {           // last CTA: all REDs visible
            float s;
            asm volatile("ld.global.cg.f32 %0, [%1];"
                         : "=f"(s) : "l"(&g_accum) : "memory");
            out[0] = s;
            asm volatile("st.global.cg.f32 [%0], 0f00000000;"
                         :: "l"(&g_accum) : "memory");   // reset accumulator
            asm volatile("st.global.cg.u32 [%0], 0;"
                         :: "l"(&g_count) : "memory");   // reset ticket
        }
    }
}

extern "C" void kernel_launch(void* const* d_in, const int* in_sizes, int n_in,
                              void* d_out, int out_size)
{
    const float4* x = (const float4*)d_in[0];
    const float4* c = (const float4*)d_in[1];
    const int4* labels4 = (const int4*)d_in[2];
    float* out = (float*)d_out;
    center_loss_kernel<<<NBLK, BLOCK>>>(x, c, labels4, out);
}

// round 10
// speedup vs baseline: 1.0295x; 1.0295x over previous
#include <cuda_runtime.h>
#include <cstdint>

// CenterLoss: mean_i ||x_i - centers[labels_i]||^2
//   = mean( ||x||^2 + ||c||^2 - 2 x.c )
// x: [4096, 512] f32, centers: [7001, 512] f32, labels: [4096] i32 -> out: [1] f32
//
// Champion structure (re-bench, unchanged): 512x256, decomposed sums with
// packed fma.rn.f32x2 (best ncu dur 7.39us, best HBM 2.0TB/s), pre-scaled
// RED + acq_rel ticket tail. Harness dur has ±0.3-0.6us noise; this kernel
// is the fastest by every intrinsic metric.

#define BATCH 4096
#define DIM 512
#define VEC (DIM / 4)     // 128 float4 per row
#define NBLK 512
#define BLOCK 256
#define SPB 8             // samples per block (4 per 128-thread half) -> exact balance

__device__ float g_accum = 0.0f;       // single pre-scaled accumulator
__device__ unsigned int g_count = 0;

// Packed fp32x2 helpers (Blackwell): one instruction = two independent fp32 FMAs.
#define PACK2(dst, lo, hi) \
    asm("mov.b64 %0, {%1, %2};" : "=l"(dst) : "f"(lo), "f"(hi))
#define FMA2(acc, a, b) \
    asm("fma.rn.f32x2 %0, %1, %2, %0;" : "+l"(acc) : "l"(a), "l"(b))
#define UNPACK2(lo, hi, src) \
    asm("mov.b64 {%0, %1}, %2;" : "=f"(lo), "=f"(hi) : "l"(src))

__global__ __launch_bounds__(BLOCK, 4)
void center_loss_kernel(const float4* __restrict__ x,
                        const float4* __restrict__ c,
                        const int4* __restrict__ labels4,
                        float* __restrict__ out)
{
    const int t = threadIdx.x;        // 0..255
    const int b = blockIdx.x;
    const int h = t >> 7;             // half 0/1 -> samples [4h, 4h+4)
    const int lane128 = t & 127;      // float4 lane within a row
    const int base = b * SPB + h * 4;

    // One int4 per half: the dependent center gather issues ASAP after this.
    const int4 lv = __ldg(&labels4[b * 2 + h]);
    const int labs[4] = { lv.x, lv.y, lv.z, lv.w };

    // Decomposed accumulation with packed f32x2 FMAs: 6 FFMA2 per sample
    // instead of 12 FFMA; every loaded float4 still consumed independently.
    uint64_t axx2 = 0ull, acc2 = 0ull, axc2 = 0ull;
#pragma unroll
    for (int s = 0; s < 4; s++) {
        float4 xv = x[(base + s) * VEC + lane128];
        uint64_t x01, x23;
        PACK2(x01, xv.x, xv.y);
        PACK2(x23, xv.z, xv.w);
        FMA2(axx2, x01, x01);
        FMA2(axx2, x23, x23);
        float4 cv = c[labs[s] * VEC + lane128];
        uint64_t c01, c23;
        PACK2(c01, cv.x, cv.y);
        PACK2(c23, cv.z, cv.w);
        FMA2(acc2, c01, c01);
        FMA2(acc2, c23, c23);
        FMA2(axc2, x01, c01);
        FMA2(axc2, x23, c23);
    }
    float a0, a1, b0, b1, d0, d1;
    UNPACK2(a0, a1, axx2);
    UNPACK2(b0, b1, acc2);
    UNPACK2(d0, d1, axc2);
    float acc = (a0 + a1) + (b0 + b1) - 2.0f * (d0 + d1);

    // Warp reduce
#pragma unroll
    for (int o = 16; o; o >>= 1) acc += __shfl_xor_sync(0xffffffffu, acc, o);

    __shared__ float ws[BLOCK / 32];
    if ((t & 31) == 0) ws[t >> 5] = acc;
    __syncthreads();

    // Thread 0: one pre-scaled RED + acq_rel ticket; last CTA reads 1 float.
    if (t == 0) {
        float p = 0.0f;
#pragma unroll
        for (int w = 0; w < BLOCK / 32; w++) p += ws[w];
        // Posted reduction (no return), pre-scaled so accumulator == mean.
        asm volatile("red.add.relaxed.gpu.global.f32 [%0], %1;"
                     :: "l"(&g_accum), "f"(p * (1.0f / (float)BATCH))
                     : "memory");
        // Release orders the RED above; acquire covers the read below.
        unsigned int v;
        asm volatile("atom.add.acq_rel.gpu.global.u32 %0, [%1], 1;"
                     : "=r"(v) : "l"(&g_count) : "memory");
        if (v == NBLK - 1) {           // last CTA: all REDs visible
            float s;
            asm volatile("ld.global.cg.f32 %0, [%1];"
                         : "=f"(s) : "l"(&g_accum) : "memory");
            out[0] = s;
            asm volatile("st.global.cg.f32 [%0], 0f00000000;"
                         :: "l"(&g_accum) : "memory");   // reset accumulator
            asm volatile("st.global.cg.u32 [%0], 0;"
                         :: "l"(&g_count) : "memory");   // reset ticket
        }
    }
}

extern "C" void kernel_launch(void* const* d_in, const int* in_sizes, int n_in,
                              void* d_out, int out_size)
{
    const float4* x = (const float4*)d_in[0];
    const float4* c = (const float4*)d_in[1];
    const int4* labels4 = (const int4*)d_in[2];
    float* out = (float*)d_out;
    center_loss_kernel<<<NBLK, BLOCK>>>(x, c, labels4, out);
}